// round 1
// baseline (speedup 1.0000x reference)
#include <cuda_runtime.h>
#include <cuda_bf16.h>
#include <cstdint>

#define NN 200000
#define EE 3200000
#define BB 512
#define LL 1000

// ------------------------ scratch (device globals, no allocs) ---------------
__device__ float g_dis[NN];
__device__ int   g_deg[NN];
__device__ float g_h[NN * 16];
__device__ float g_agg[NN * 16];
__device__ float g_feat[NN * 16];
__device__ float g_pool[BB * 16];
__device__ float g_t1[BB * 1024];
__device__ float g_xc[BB * 256];
__device__ float g_c1[BB * 32 * 331];
__device__ float g_c2[BB * 64 * 108];
__device__ float g_c3[BB * 128];
__device__ float g_f1[BB * 1024];
__device__ float g_f2[BB * 512];

// ------------------------ graph branch --------------------------------------
__global__ void deg_kernel(const int* __restrict__ ei, int* __restrict__ deg) {
    int e = blockIdx.x * blockDim.x + threadIdx.x;
    if (e >= EE) return;
    atomicAdd(&deg[ei[EE + e]], 1);
}

__global__ void dis_kernel(const int* __restrict__ deg, float* __restrict__ dis) {
    int i = blockIdx.x * blockDim.x + threadIdx.x;
    if (i >= NN) return;
    dis[i] = rsqrtf((float)deg[i] + 1.0f);
}

template <int FI, int FO>
__global__ void node_transform(const float* __restrict__ in, const float* __restrict__ W,
                               float* __restrict__ h) {
    __shared__ float Ws[FI * FO];
    int tid = threadIdx.x;
    if (tid < FI * FO) Ws[tid] = W[tid];
    __syncthreads();
    int i = blockIdx.x * blockDim.x + tid;
    if (i >= NN) return;
    float xi[FI];
#pragma unroll
    for (int f = 0; f < FI; f++) xi[f] = in[(size_t)i * FI + f];
#pragma unroll
    for (int fo = 0; fo < FO; fo++) {
        float s = 0.f;
#pragma unroll
        for (int fi = 0; fi < FI; fi++) s = fmaf(xi[fi], Ws[fi * FO + fo], s);
        h[(size_t)i * FO + fo] = s;
    }
}

template <int F>
__global__ void scatter_kernel(const int* __restrict__ ei, const float* __restrict__ dis,
                               const float* __restrict__ h, float* __restrict__ agg) {
    int e = blockIdx.x * blockDim.x + threadIdx.x;
    if (e >= EE) return;
    int s = __ldg(&ei[e]);
    int d = __ldg(&ei[EE + e]);
    float c = __ldg(&dis[s]) * __ldg(&dis[d]);
    const float4* hs = reinterpret_cast<const float4*>(h + (size_t)s * F);
    float* ad = agg + (size_t)d * F;
#pragma unroll
    for (int q = 0; q < F / 4; q++) {
        float4 m = hs[q];
        m.x *= c; m.y *= c; m.z *= c; m.w *= c;
        asm volatile("red.global.add.v4.f32 [%0], {%1,%2,%3,%4};"
                     :: "l"(ad + q * 4), "f"(m.x), "f"(m.y), "f"(m.z), "f"(m.w)
                     : "memory");
    }
}

template <int FO>
__global__ void combine_kernel(const float* __restrict__ agg, const float* __restrict__ h,
                               const float* __restrict__ dis, const float* __restrict__ bias,
                               float* __restrict__ outf) {
    long idx = (long)blockIdx.x * blockDim.x + threadIdx.x;
    if (idx >= (long)NN * FO) return;
    int i = (int)(idx / FO);
    int f = (int)(idx - (long)i * FO);
    float dd = dis[i];
    float v = agg[idx] + dd * dd * h[idx] + bias[f];
    outf[idx] = fmaxf(v, 0.f);
}

__global__ void pool_kernel(const float* __restrict__ feat, const int* __restrict__ batch,
                            float* __restrict__ pool) {
    int i = blockIdx.x * blockDim.x + threadIdx.x;
    if (i >= NN) return;
    int bb = batch[i];
    int* p = reinterpret_cast<int*>(pool + bb * 16);
#pragma unroll
    for (int f = 0; f < 16; f++)
        atomicMax(&p[f], __float_as_int(feat[(size_t)i * 16 + f]));
}

// ------------------------ generic GEMM (bias + optional relu) ---------------
__global__ void gemm_kernel(const float* __restrict__ A, const float* __restrict__ W,
                            const float* __restrict__ bias, float* __restrict__ C,
                            int M, int K, int Nc, int ldc, int coloff, int relu) {
    const int BM = 64, BN = 64, BK = 8;
    __shared__ float As[BK][BM];
    __shared__ float Bs[BK][BN];
    int tid = threadIdx.x;
    int tc = tid & 15, tr = tid >> 4;
    int brow = blockIdx.y * BM, bcol = blockIdx.x * BN;
    float acc[4][4] = {};
    for (int k0 = 0; k0 < K; k0 += BK) {
        for (int i = tid; i < BM * BK; i += 256) {
            int kk = i & 7, m = i >> 3;
            int gr = brow + m, gc = k0 + kk;
            As[kk][m] = (gr < M && gc < K) ? A[(size_t)gr * K + gc] : 0.f;
        }
        for (int i = tid; i < BN * BK; i += 256) {
            int n = i & 63, kk = i >> 6;
            int gc = bcol + n, gr = k0 + kk;
            Bs[kk][n] = (gr < K && gc < Nc) ? W[(size_t)gr * Nc + gc] : 0.f;
        }
        __syncthreads();
#pragma unroll
        for (int kk = 0; kk < BK; kk++) {
            float a[4], bv[4];
#pragma unroll
            for (int u = 0; u < 4; u++) { a[u] = As[kk][tr * 4 + u]; bv[u] = Bs[kk][tc * 4 + u]; }
#pragma unroll
            for (int u = 0; u < 4; u++)
#pragma unroll
                for (int v = 0; v < 4; v++) acc[u][v] = fmaf(a[u], bv[v], acc[u][v]);
        }
        __syncthreads();
    }
#pragma unroll
    for (int u = 0; u < 4; u++) {
        int r = brow + tr * 4 + u;
        if (r >= M) continue;
#pragma unroll
        for (int v = 0; v < 4; v++) {
            int c = bcol + tc * 4 + v;
            if (c >= Nc) continue;
            float val = acc[u][v] + bias[c];
            if (relu) val = fmaxf(val, 0.f);
            C[(size_t)r * ldc + coloff + c] = val;
        }
    }
}

// ------------------------ conv stack ----------------------------------------
// conv1: in target [B,L,5] -> fused conv(k=8)+relu+maxpool3 -> [B,32,331]
__global__ void conv1_kernel(const float* __restrict__ tgt, const float* __restrict__ K1,
                             const float* __restrict__ cb1, float* __restrict__ out) {
    __shared__ float in_s[5][80];
    __shared__ float w_s[5 * 8 * 32];
    __shared__ float b_s[32];
    int b = blockIdx.x;
    int g0 = blockIdx.y * 8;
    int tx = threadIdx.x, ty = threadIdx.y;
    int tid = ty * 32 + tx;
    int L0 = g0 * 9;
    for (int i = tid; i < 400; i += 256) {
        int c = i % 5, p = i / 5;
        int l = L0 + p;
        in_s[c][p] = (l < LL) ? tgt[(size_t)b * (LL * 5) + l * 5 + c] : 0.f;
    }
    for (int i = tid; i < 1280; i += 256) {
        int oc = i / 40, r = i % 40, ic = r / 8, k = r % 8;
        w_s[(ic * 8 + k) * 32 + oc] = K1[i];
    }
    if (tid < 32) b_s[tid] = cb1[tid];
    __syncthreads();

    int grp = g0 + ty;
    float acc[9] = {0.f, 0.f, 0.f, 0.f, 0.f, 0.f, 0.f, 0.f, 0.f};
#pragma unroll
    for (int ic = 0; ic < 5; ic++) {
        float xr[16];
#pragma unroll
        for (int i = 0; i < 16; i++) xr[i] = in_s[ic][ty * 9 + i];
#pragma unroll
        for (int k = 0; k < 8; k++) {
            float w = w_s[(ic * 8 + k) * 32 + tx];
#pragma unroll
            for (int l = 0; l < 9; l++) acc[l] = fmaf(w, xr[l + k], acc[l]);
        }
    }
    float bb = b_s[tx];
#pragma unroll
    for (int p = 0; p < 3; p++) {
        int po = grp * 3 + p;
        if (po < 331) {
            float v = fmaxf(fmaxf(acc[3 * p], acc[3 * p + 1]), acc[3 * p + 2]) + bb;
            out[((size_t)b * 32 + tx) * 331 + po] = fmaxf(v, 0.f);
        }
    }
}

// conv2: [B,32,331] -> conv(k=8)+relu+pool3 -> [B,64,108]
__global__ void conv2_kernel(const float* __restrict__ c1, const float* __restrict__ K2,
                             const float* __restrict__ cb2, float* __restrict__ out) {
    __shared__ float in_s[32][80];
    __shared__ float w_s[32 * 8 * 32];
    __shared__ float b_s[32];
    int b = blockIdx.x;
    int g0 = blockIdx.y * 8;
    int ocz = blockIdx.z;
    int tx = threadIdx.x, ty = threadIdx.y;
    int tid = ty * 32 + tx;
    int L0 = g0 * 9;
    for (int i = tid; i < 32 * 80; i += 256) {
        int ic = i / 80, p = i % 80;
        int l = L0 + p;
        in_s[ic][p] = (l < 331) ? c1[((size_t)b * 32 + ic) * 331 + l] : 0.f;
    }
    for (int i = tid; i < 8192; i += 256) {
        int oc = i / 256, r = i % 256;
        w_s[r * 32 + oc] = K2[((size_t)(ocz * 32 + oc)) * 256 + r];
    }
    if (tid < 32) b_s[tid] = cb2[ocz * 32 + tid];
    __syncthreads();

    int grp = g0 + ty;
    float acc[9] = {0.f, 0.f, 0.f, 0.f, 0.f, 0.f, 0.f, 0.f, 0.f};
    for (int ic = 0; ic < 32; ic++) {
        float xr[16];
#pragma unroll
        for (int i = 0; i < 16; i++) xr[i] = in_s[ic][ty * 9 + i];
#pragma unroll
        for (int k = 0; k < 8; k++) {
            float w = w_s[(ic * 8 + k) * 32 + tx];
#pragma unroll
            for (int l = 0; l < 9; l++) acc[l] = fmaf(w, xr[l + k], acc[l]);
        }
    }
    if (grp < 36) {
        float bb = b_s[tx];
        int oc = ocz * 32 + tx;
#pragma unroll
        for (int p = 0; p < 3; p++) {
            int po = grp * 3 + p;
            float v = fmaxf(fmaxf(acc[3 * p], acc[3 * p + 1]), acc[3 * p + 2]) + bb;
            out[((size_t)b * 64 + oc) * 108 + po] = fmaxf(v, 0.f);
        }
    }
}

// conv3: [B,64,108] -> conv(k=8)+relu+pool3 -> mean over 33 -> [B,128]
#define CONV3_SMEM ((6912 + 16384 + 32) * 4)
__global__ void conv3_kernel(const float* __restrict__ c2, const float* __restrict__ K3,
                             const float* __restrict__ cb3, float* __restrict__ c3) {
    extern __shared__ float sm[];
    float* in_s = sm;               // 64*108
    float* w_s = sm + 6912;         // 64*8*32 : [(ic*8+k)*32+oc]
    float* b_s = w_s + 16384;       // 32
    int b = blockIdx.x;
    int ocz = blockIdx.y;
    int tx = threadIdx.x, ty = threadIdx.y;
    int tid = ty * 32 + tx;         // 352 threads
    for (int i = tid; i < 6912; i += 352) in_s[i] = c2[(size_t)b * 6912 + i];
    for (int i = tid; i < 16384; i += 352) {
        int oc = i / 512, r = i % 512;
        w_s[r * 32 + oc] = K3[((size_t)(ocz * 32 + oc)) * 512 + r];
    }
    if (tid < 32) b_s[tid] = cb3[ocz * 32 + tid];
    __syncthreads();

    float acc[9] = {0.f, 0.f, 0.f, 0.f, 0.f, 0.f, 0.f, 0.f, 0.f};
    for (int ic = 0; ic < 64; ic++) {
        float xr[16];
#pragma unroll
        for (int i = 0; i < 16; i++) xr[i] = in_s[ic * 108 + ty * 9 + i];
#pragma unroll
        for (int k = 0; k < 8; k++) {
            float w = w_s[(ic * 8 + k) * 32 + tx];
#pragma unroll
            for (int l = 0; l < 9; l++) acc[l] = fmaf(w, xr[l + k], acc[l]);
        }
    }
    float bb = b_s[tx];
    float s = 0.f;
#pragma unroll
    for (int p = 0; p < 3; p++) {
        float v = fmaxf(fmaxf(acc[3 * p], acc[3 * p + 1]), acc[3 * p + 2]) + bb;
        s += fmaxf(v, 0.f);
    }
    atomicAdd(&c3[(size_t)b * 128 + ocz * 32 + tx], s * (1.0f / 33.0f));
}

// ------------------------ host orchestration --------------------------------
extern "C" void kernel_launch(void* const* d_in, const int* in_sizes, int n_in,
                              void* d_out, int out_size) {
    const float* x    = (const float*)d_in[0];
    const int*   ei   = (const int*)d_in[1];
    const int*   batch= (const int*)d_in[2];
    const float* tgt  = (const float*)d_in[3];
    const float* W1 = (const float*)d_in[4];   const float* b1 = (const float*)d_in[5];
    const float* W2 = (const float*)d_in[6];   const float* b2 = (const float*)d_in[7];
    const float* W3 = (const float*)d_in[8];   const float* b3 = (const float*)d_in[9];
    const float* Wg1= (const float*)d_in[10];  const float* bg1= (const float*)d_in[11];
    const float* Wg2= (const float*)d_in[12];  const float* bg2= (const float*)d_in[13];
    const float* K1 = (const float*)d_in[14];  const float* cb1= (const float*)d_in[15];
    const float* K2 = (const float*)d_in[16];  const float* cb2= (const float*)d_in[17];
    const float* K3 = (const float*)d_in[18];  const float* cb3= (const float*)d_in[19];
    const float* Wxt= (const float*)d_in[20];  const float* bxt= (const float*)d_in[21];
    const float* Wf1= (const float*)d_in[22];  const float* bf1= (const float*)d_in[23];
    const float* Wf2= (const float*)d_in[24];  const float* bf2= (const float*)d_in[25];
    const float* Wo = (const float*)d_in[26];  const float* bo = (const float*)d_in[27];
    float* out = (float*)d_out;

    float *p_dis, *p_h, *p_agg, *p_feat, *p_pool, *p_t1, *p_xc, *p_c1, *p_c2, *p_c3, *p_f1, *p_f2;
    int* p_deg;
    cudaGetSymbolAddress((void**)&p_dis, g_dis);
    cudaGetSymbolAddress((void**)&p_deg, g_deg);
    cudaGetSymbolAddress((void**)&p_h, g_h);
    cudaGetSymbolAddress((void**)&p_agg, g_agg);
    cudaGetSymbolAddress((void**)&p_feat, g_feat);
    cudaGetSymbolAddress((void**)&p_pool, g_pool);
    cudaGetSymbolAddress((void**)&p_t1, g_t1);
    cudaGetSymbolAddress((void**)&p_xc, g_xc);
    cudaGetSymbolAddress((void**)&p_c1, g_c1);
    cudaGetSymbolAddress((void**)&p_c2, g_c2);
    cudaGetSymbolAddress((void**)&p_c3, g_c3);
    cudaGetSymbolAddress((void**)&p_f1, g_f1);
    cudaGetSymbolAddress((void**)&p_f2, g_f2);

    const int TPB = 256;
    const int gE = (EE + TPB - 1) / TPB;
    const int gN = (NN + TPB - 1) / TPB;

    // ---- degrees / normalization ----
    cudaMemsetAsync(p_deg, 0, NN * sizeof(int));
    deg_kernel<<<gE, TPB>>>(ei, p_deg);
    dis_kernel<<<gN, TPB>>>(p_deg, p_dis);

    // ---- GCN layer 1 (4 -> 4) ----
    node_transform<4, 4><<<gN, TPB>>>(x, W1, p_h);
    cudaMemsetAsync(p_agg, 0, (size_t)NN * 4 * sizeof(float));
    scatter_kernel<4><<<gE, TPB>>>(ei, p_dis, p_h, p_agg);
    combine_kernel<4><<<((long)NN * 4 + TPB - 1) / TPB, TPB>>>(p_agg, p_h, p_dis, b1, p_feat);

    // ---- GCN layer 2 (4 -> 8) ----
    node_transform<4, 8><<<gN, TPB>>>(p_feat, W2, p_h);
    cudaMemsetAsync(p_agg, 0, (size_t)NN * 8 * sizeof(float));
    scatter_kernel<8><<<gE, TPB>>>(ei, p_dis, p_h, p_agg);
    combine_kernel<8><<<((long)NN * 8 + TPB - 1) / TPB, TPB>>>(p_agg, p_h, p_dis, b2, p_feat);

    // ---- GCN layer 3 (8 -> 16) ----
    node_transform<8, 16><<<gN, TPB>>>(p_feat, W3, p_h);
    cudaMemsetAsync(p_agg, 0, (size_t)NN * 16 * sizeof(float));
    scatter_kernel<16><<<gE, TPB>>>(ei, p_dis, p_h, p_agg);
    combine_kernel<16><<<((long)NN * 16 + TPB - 1) / TPB, TPB>>>(p_agg, p_h, p_dis, b3, p_feat);

    // ---- global max pool + graph MLP ----
    cudaMemsetAsync(p_pool, 0, BB * 16 * sizeof(float));
    pool_kernel<<<gN, TPB>>>(p_feat, batch, p_pool);
    gemm_kernel<<<dim3(16, 8), 256>>>(p_pool, Wg1, bg1, p_t1, BB, 16, 1024, 1024, 0, 1);
    gemm_kernel<<<dim3(2, 8), 256>>>(p_t1, Wg2, bg2, p_xc, BB, 1024, 128, 256, 0, 0);

    // ---- conv branch ----
    conv1_kernel<<<dim3(BB, 14), dim3(32, 8)>>>(tgt, K1, cb1, p_c1);
    conv2_kernel<<<dim3(BB, 5, 2), dim3(32, 8)>>>(p_c1, K2, cb2, p_c2);
    cudaMemsetAsync(p_c3, 0, BB * 128 * sizeof(float));
    cudaFuncSetAttribute(conv3_kernel, cudaFuncAttributeMaxDynamicSharedMemorySize, CONV3_SMEM);
    conv3_kernel<<<dim3(BB, 4), dim3(32, 11), CONV3_SMEM>>>(p_c2, K3, cb3, p_c3);
    gemm_kernel<<<dim3(2, 8), 256>>>(p_c3, Wxt, bxt, p_xc, BB, 128, 128, 256, 128, 1);

    // ---- fusion head ----
    gemm_kernel<<<dim3(16, 8), 256>>>(p_xc, Wf1, bf1, p_f1, BB, 256, 1024, 1024, 0, 1);
    gemm_kernel<<<dim3(8, 8), 256>>>(p_f1, Wf2, bf2, p_f2, BB, 1024, 512, 512, 0, 1);
    gemm_kernel<<<dim3(1, 8), 256>>>(p_f2, Wo, bo, out, BB, 512, 2, 2, 0, 0);
}

// round 2
// speedup vs baseline: 1.1597x; 1.1597x over previous
#include <cuda_runtime.h>
#include <cuda_bf16.h>
#include <cstdint>

#define NN 200000
#define EE 3200000
#define BB 512
#define LL 1000

typedef unsigned long long ull;

// ------------------------ scratch (device globals, no allocs) ---------------
__device__ float g_dis[NN];
__device__ int   g_deg[NN];
__device__ float g_h[NN * 16];     // ping: dis-scaled transformed features
__device__ float g_feat[NN * 16];  // pong
__device__ float g_agg[NN * 16];
__device__ float g_pool[BB * 16];
__device__ float g_t1[BB * 1024];
__device__ float g_xc[BB * 256];
__device__ float g_c1[BB * 32 * 331];
__device__ float g_c2[BB * 64 * 108];
__device__ float g_c3[BB * 128];
__device__ float g_f1[BB * 1024];
__device__ float g_f2[BB * 512];

// ------------------------ f32x2 helpers --------------------------------------
__device__ __forceinline__ ull pk2(float lo, float hi) {
    ull r; asm("mov.b64 %0, {%1, %2};" : "=l"(r) : "f"(lo), "f"(hi)); return r;
}
__device__ __forceinline__ float2 upk2(ull v) {
    float2 r; asm("mov.b64 {%0, %1}, %2;" : "=f"(r.x), "=f"(r.y) : "l"(v)); return r;
}
__device__ __forceinline__ void ffma2(ull& d, ull a, ull b) {
    asm("fma.rn.f32x2 %0, %1, %2, %0;" : "+l"(d) : "l"(a), "l"(b));
}

// ------------------------ graph branch --------------------------------------
__global__ void deg_kernel(const int* __restrict__ ei, int* __restrict__ deg) {
    int e = blockIdx.x * blockDim.x + threadIdx.x;
    if (e >= EE) return;
    atomicAdd(&deg[ei[EE + e]], 1);
}

__global__ void dis_kernel(const int* __restrict__ deg, float* __restrict__ dis) {
    int i = blockIdx.x * blockDim.x + threadIdx.x;
    if (i >= NN) return;
    dis[i] = rsqrtf((float)deg[i] + 1.0f);
}

// hs = dis[i] * (x @ W1)
__global__ void transform1(const float* __restrict__ x, const float* __restrict__ W,
                           const float* __restrict__ dis, float* __restrict__ hs) {
    __shared__ float Ws[16];
    int tid = threadIdx.x;
    if (tid < 16) Ws[tid] = W[tid];
    __syncthreads();
    int i = blockIdx.x * blockDim.x + tid;
    if (i >= NN) return;
    float xi[4];
#pragma unroll
    for (int f = 0; f < 4; f++) xi[f] = x[(size_t)i * 4 + f];
    float dd = dis[i];
#pragma unroll
    for (int fo = 0; fo < 4; fo++) {
        float s = 0.f;
#pragma unroll
        for (int fi = 0; fi < 4; fi++) s = fmaf(xi[fi], Ws[fi * 4 + fo], s);
        hs[(size_t)i * 4 + fo] = dd * s;
    }
}

// pure copy-scatter: agg[dst] += hs[src]   (all normalization folded elsewhere)
template <int F>
__global__ void scatter_kernel(const int* __restrict__ ei, const float* __restrict__ hs,
                               float* __restrict__ agg) {
    int e = blockIdx.x * blockDim.x + threadIdx.x;
    if (e >= EE) return;
    int s = __ldg(&ei[e]);
    int d = __ldg(&ei[EE + e]);
    const float4* p = reinterpret_cast<const float4*>(hs + (size_t)s * F);
    float* ad = agg + (size_t)d * F;
#pragma unroll
    for (int q = 0; q < F / 4; q++) {
        float4 m = p[q];
        asm volatile("red.global.add.v4.f32 [%0], {%1,%2,%3,%4};"
                     :: "l"(ad + q * 4), "f"(m.x), "f"(m.y), "f"(m.z), "f"(m.w)
                     : "memory");
    }
}

// feat = relu(dis*(agg+hs)+b); hs_next = dis * (feat @ W)
template <int F, int FO>
__global__ void combine_transform(const float* __restrict__ agg, const float* __restrict__ hs,
                                  const float* __restrict__ dis, const float* __restrict__ bias,
                                  const float* __restrict__ W, float* __restrict__ out) {
    __shared__ float Ws[F * FO];
    __shared__ float bs[F];
    int tid = threadIdx.x;
    if (tid < F * FO) Ws[tid] = W[tid];
    if (tid < F) bs[tid] = bias[tid];
    __syncthreads();
    int i = blockIdx.x * blockDim.x + tid;
    if (i >= NN) return;
    float dd = dis[i];
    float v[F];
#pragma unroll
    for (int f = 0; f < F; f++)
        v[f] = fmaxf(dd * (agg[(size_t)i * F + f] + hs[(size_t)i * F + f]) + bs[f], 0.f);
#pragma unroll
    for (int fo = 0; fo < FO; fo++) {
        float s = 0.f;
#pragma unroll
        for (int f = 0; f < F; f++) s = fmaf(v[f], Ws[f * FO + fo], s);
        out[(size_t)i * FO + fo] = dd * s;
    }
}

// final layer: feat = relu(dis*(agg+hs)+b3); pool = segment-max(feat, batch)
__global__ void combine_pool(const float* __restrict__ agg, const float* __restrict__ hs,
                             const float* __restrict__ dis, const float* __restrict__ bias,
                             const int* __restrict__ batch, float* __restrict__ pool) {
    __shared__ float bs[16];
    int tid = threadIdx.x;
    if (tid < 16) bs[tid] = bias[tid];
    __syncthreads();
    int i = blockIdx.x * blockDim.x + tid;
    if (i >= NN) return;
    float dd = dis[i];
    float v[16];
#pragma unroll
    for (int f = 0; f < 16; f++)
        v[f] = fmaxf(dd * (agg[(size_t)i * 16 + f] + hs[(size_t)i * 16 + f]) + bs[f], 0.f);
    int bb = batch[i];
    unsigned m = __activemask();
    bool uni = false;
    if (m == 0xffffffffu) {
        int bb0 = __shfl_sync(0xffffffffu, bb, 0);
        uni = __all_sync(0xffffffffu, bb == bb0);
    }
    int* p = reinterpret_cast<int*>(pool + (size_t)bb * 16);
    if (uni) {
#pragma unroll
        for (int f = 0; f < 16; f++) {
            float t = v[f];
#pragma unroll
            for (int o = 16; o; o >>= 1) t = fmaxf(t, __shfl_xor_sync(0xffffffffu, t, o));
            v[f] = t;
        }
        if ((tid & 31) == 0)
#pragma unroll
            for (int f = 0; f < 16; f++) atomicMax(&p[f], __float_as_int(v[f]));
    } else {
#pragma unroll
        for (int f = 0; f < 16; f++) atomicMax(&p[f], __float_as_int(v[f]));
    }
}

// ------------------------ generic GEMM (f32x2, bias + optional relu) --------
__global__ void gemm_kernel(const float* __restrict__ A, const float* __restrict__ W,
                            const float* __restrict__ bias, float* __restrict__ C,
                            int M, int K, int Nc, int ldc, int coloff, int relu) {
    const int BM = 64, BN = 64, BK = 8;
    __shared__ __align__(16) float As[BK][BM];
    __shared__ __align__(16) float Bs[BK][BN];
    int tid = threadIdx.x;
    int tc = tid & 15, tr = tid >> 4;
    int brow = blockIdx.y * BM, bcol = blockIdx.x * BN;
    ull acc[4][2] = {};
    for (int k0 = 0; k0 < K; k0 += BK) {
        for (int i = tid; i < BM * BK; i += 256) {
            int kk = i & 7, m = i >> 3;
            int gr = brow + m, gc = k0 + kk;
            As[kk][m] = (gr < M && gc < K) ? A[(size_t)gr * K + gc] : 0.f;
        }
        for (int i = tid; i < BN * BK; i += 256) {
            int n = i & 63, kk = i >> 6;
            int gc = bcol + n, gr = k0 + kk;
            Bs[kk][n] = (gr < K && gc < Nc) ? W[(size_t)gr * Nc + gc] : 0.f;
        }
        __syncthreads();
#pragma unroll
        for (int kk = 0; kk < BK; kk++) {
            ull b0 = *reinterpret_cast<const ull*>(&Bs[kk][tc * 4]);
            ull b1 = *reinterpret_cast<const ull*>(&Bs[kk][tc * 4 + 2]);
#pragma unroll
            for (int u = 0; u < 4; u++) {
                float av = As[kk][tr * 4 + u];
                ull a2 = pk2(av, av);
                ffma2(acc[u][0], b0, a2);
                ffma2(acc[u][1], b1, a2);
            }
        }
        __syncthreads();
    }
#pragma unroll
    for (int u = 0; u < 4; u++) {
        int r = brow + tr * 4 + u;
        if (r >= M) continue;
#pragma unroll
        for (int v2 = 0; v2 < 2; v2++) {
            float2 pv = upk2(acc[u][v2]);
            float vals[2] = {pv.x, pv.y};
#pragma unroll
            for (int w = 0; w < 2; w++) {
                int c = bcol + tc * 4 + v2 * 2 + w;
                if (c >= Nc) continue;
                float val = vals[w] + bias[c];
                if (relu) val = fmaxf(val, 0.f);
                C[(size_t)r * ldc + coloff + c] = val;
            }
        }
    }
}

// ------------------------ conv inner (f32x2) ---------------------------------
// per input channel: 9 conv outputs (3 pooled) x 8 taps, packed 2-wide.
__device__ __forceinline__ void ic_update(const float* __restrict__ xr,
                                          const float* __restrict__ w, ull acc[5]) {
    ull e[8], o[8];
#pragma unroll
    for (int i = 0; i < 8; i++) e[i] = pk2(xr[2 * i], xr[2 * i + 1]);
#pragma unroll
    for (int i = 0; i < 7; i++) o[i] = pk2(xr[2 * i + 1], xr[2 * i + 2]);
    o[7] = pk2(xr[15], 0.f);
#pragma unroll
    for (int k = 0; k < 8; k++) {
        float wv = w[k * 32];
        ull w2 = pk2(wv, wv);
        const ull* xp = (k & 1) ? &o[k >> 1] : &e[k >> 1];
#pragma unroll
        for (int j = 0; j < 5; j++) ffma2(acc[j], xp[j], w2);
    }
}

__device__ __forceinline__ void unpack9(const ull acc[5], float a[9]) {
#pragma unroll
    for (int j = 0; j < 4; j++) {
        float2 t = upk2(acc[j]);
        a[2 * j] = t.x; a[2 * j + 1] = t.y;
    }
    a[8] = upk2(acc[4]).x;
}

// conv1: target [B,L,5] -> conv(k=8)+relu+maxpool3 -> [B,32,331]
__global__ void conv1_kernel(const float* __restrict__ tgt, const float* __restrict__ K1,
                             const float* __restrict__ cb1, float* __restrict__ out) {
    __shared__ float in_s[5][80];
    __shared__ float w_s[5 * 8 * 32];
    __shared__ float b_s[32];
    int b = blockIdx.x;
    int g0 = blockIdx.y * 8;
    int tx = threadIdx.x, ty = threadIdx.y;
    int tid = ty * 32 + tx;
    int L0 = g0 * 9;
    for (int i = tid; i < 400; i += 256) {
        int c = i % 5, p = i / 5;
        int l = L0 + p;
        in_s[c][p] = (l < LL) ? tgt[(size_t)b * (LL * 5) + l * 5 + c] : 0.f;
    }
    for (int i = tid; i < 1280; i += 256) {
        int oc = i / 40, r = i % 40;
        w_s[r * 32 + oc] = K1[i];
    }
    if (tid < 32) b_s[tid] = cb1[tid];
    __syncthreads();

    ull acc[5] = {};
#pragma unroll
    for (int ic = 0; ic < 5; ic++) {
        float xr[16];
#pragma unroll
        for (int i = 0; i < 16; i++) xr[i] = in_s[ic][ty * 9 + i];
        ic_update(xr, &w_s[ic * 256 + tx], acc);
    }
    float a[9]; unpack9(acc, a);
    float bb = b_s[tx];
    int grp = g0 + ty;
#pragma unroll
    for (int p = 0; p < 3; p++) {
        int po = grp * 3 + p;
        if (po < 331) {
            float v = fmaxf(fmaxf(a[3 * p], a[3 * p + 1]), a[3 * p + 2]) + bb;
            out[((size_t)b * 32 + tx) * 331 + po] = fmaxf(v, 0.f);
        }
    }
}

// conv2: [B,32,331] -> conv(k=8)+relu+pool3 -> [B,64,108]
__global__ void conv2_kernel(const float* __restrict__ c1, const float* __restrict__ K2,
                             const float* __restrict__ cb2, float* __restrict__ out) {
    __shared__ float in_s[32][80];
    __shared__ float w_s[32 * 8 * 32];
    __shared__ float b_s[32];
    int b = blockIdx.x;
    int g0 = blockIdx.y * 8;
    int ocz = blockIdx.z;
    int tx = threadIdx.x, ty = threadIdx.y;
    int tid = ty * 32 + tx;
    int L0 = g0 * 9;
    for (int i = tid; i < 32 * 80; i += 256) {
        int ic = i / 80, p = i % 80;
        int l = L0 + p;
        in_s[ic][p] = (l < 331) ? c1[((size_t)b * 32 + ic) * 331 + l] : 0.f;
    }
    for (int i = tid; i < 8192; i += 256) {
        int oc = i / 256, r = i % 256;
        w_s[r * 32 + oc] = K2[((size_t)(ocz * 32 + oc)) * 256 + r];
    }
    if (tid < 32) b_s[tid] = cb2[ocz * 32 + tid];
    __syncthreads();

    int grp = g0 + ty;
    ull acc[5] = {};
#pragma unroll 4
    for (int ic = 0; ic < 32; ic++) {
        float xr[16];
#pragma unroll
        for (int i = 0; i < 16; i++) xr[i] = in_s[ic][ty * 9 + i];
        ic_update(xr, &w_s[ic * 256 + tx], acc);
    }
    if (grp < 36) {
        float a[9]; unpack9(acc, a);
        float bb = b_s[tx];
        int oc = ocz * 32 + tx;
#pragma unroll
        for (int p = 0; p < 3; p++) {
            int po = grp * 3 + p;
            float v = fmaxf(fmaxf(a[3 * p], a[3 * p + 1]), a[3 * p + 2]) + bb;
            out[((size_t)b * 64 + oc) * 108 + po] = fmaxf(v, 0.f);
        }
    }
}

// conv3: [B,64,108] -> conv(k=8)+relu+pool3 -> mean over 33 -> [B,128]
#define CONV3_SMEM ((6912 + 16384 + 32) * 4)
__global__ void conv3_kernel(const float* __restrict__ c2, const float* __restrict__ K3,
                             const float* __restrict__ cb3, float* __restrict__ c3) {
    extern __shared__ float sm[];
    float* in_s = sm;               // 64*108
    float* w_s = sm + 6912;         // [(ic*8+k)*32+oc]
    float* b_s = w_s + 16384;
    int b = blockIdx.x;
    int ocz = blockIdx.y;
    int tx = threadIdx.x, ty = threadIdx.y;
    int tid = ty * 32 + tx;         // 352 threads
    for (int i = tid; i < 6912; i += 352) in_s[i] = c2[(size_t)b * 6912 + i];
    for (int i = tid; i < 16384; i += 352) {
        int oc = i / 512, r = i % 512;
        w_s[r * 32 + oc] = K3[((size_t)(ocz * 32 + oc)) * 512 + r];
    }
    if (tid < 32) b_s[tid] = cb3[ocz * 32 + tid];
    __syncthreads();

    ull acc[5] = {};
#pragma unroll 4
    for (int ic = 0; ic < 64; ic++) {
        float xr[16];
#pragma unroll
        for (int i = 0; i < 16; i++) xr[i] = in_s[ic * 108 + ty * 9 + i];
        ic_update(xr, &w_s[ic * 256 + tx], acc);
    }
    float a[9]; unpack9(acc, a);
    float bb = b_s[tx];
    float s = 0.f;
#pragma unroll
    for (int p = 0; p < 3; p++) {
        float v = fmaxf(fmaxf(a[3 * p], a[3 * p + 1]), a[3 * p + 2]) + bb;
        s += fmaxf(v, 0.f);
    }
    atomicAdd(&c3[(size_t)b * 128 + ocz * 32 + tx], s * (1.0f / 33.0f));
}

// ------------------------ stream fork/join context --------------------------
struct Ctx {
    cudaStream_t s2 = nullptr;
    cudaEvent_t eF = nullptr, eJ = nullptr;
    bool ok = false;
    Ctx() {
        ok = (cudaStreamCreateWithFlags(&s2, cudaStreamNonBlocking) == cudaSuccess) &&
             (cudaEventCreateWithFlags(&eF, cudaEventDisableTiming) == cudaSuccess) &&
             (cudaEventCreateWithFlags(&eJ, cudaEventDisableTiming) == cudaSuccess);
    }
};
static Ctx g_ctx;

// ------------------------ host orchestration --------------------------------
extern "C" void kernel_launch(void* const* d_in, const int* in_sizes, int n_in,
                              void* d_out, int out_size) {
    const float* x    = (const float*)d_in[0];
    const int*   ei   = (const int*)d_in[1];
    const int*   batch= (const int*)d_in[2];
    const float* tgt  = (const float*)d_in[3];
    const float* W1 = (const float*)d_in[4];   const float* b1 = (const float*)d_in[5];
    const float* W2 = (const float*)d_in[6];   const float* b2 = (const float*)d_in[7];
    const float* W3 = (const float*)d_in[8];   const float* b3 = (const float*)d_in[9];
    const float* Wg1= (const float*)d_in[10];  const float* bg1= (const float*)d_in[11];
    const float* Wg2= (const float*)d_in[12];  const float* bg2= (const float*)d_in[13];
    const float* K1 = (const float*)d_in[14];  const float* cb1= (const float*)d_in[15];
    const float* K2 = (const float*)d_in[16];  const float* cb2= (const float*)d_in[17];
    const float* K3 = (const float*)d_in[18];  const float* cb3= (const float*)d_in[19];
    const float* Wxt= (const float*)d_in[20];  const float* bxt= (const float*)d_in[21];
    const float* Wf1= (const float*)d_in[22];  const float* bf1= (const float*)d_in[23];
    const float* Wf2= (const float*)d_in[24];  const float* bf2= (const float*)d_in[25];
    const float* Wo = (const float*)d_in[26];  const float* bo = (const float*)d_in[27];
    float* out = (float*)d_out;

    float *p_dis, *p_h, *p_feat, *p_agg, *p_pool, *p_t1, *p_xc, *p_c1, *p_c2, *p_c3, *p_f1, *p_f2;
    int* p_deg;
    cudaGetSymbolAddress((void**)&p_dis, g_dis);
    cudaGetSymbolAddress((void**)&p_deg, g_deg);
    cudaGetSymbolAddress((void**)&p_h, g_h);
    cudaGetSymbolAddress((void**)&p_feat, g_feat);
    cudaGetSymbolAddress((void**)&p_agg, g_agg);
    cudaGetSymbolAddress((void**)&p_pool, g_pool);
    cudaGetSymbolAddress((void**)&p_t1, g_t1);
    cudaGetSymbolAddress((void**)&p_xc, g_xc);
    cudaGetSymbolAddress((void**)&p_c1, g_c1);
    cudaGetSymbolAddress((void**)&p_c2, g_c2);
    cudaGetSymbolAddress((void**)&p_c3, g_c3);
    cudaGetSymbolAddress((void**)&p_f1, g_f1);
    cudaGetSymbolAddress((void**)&p_f2, g_f2);

    const int TPB = 256;
    const int gE = (EE + TPB - 1) / TPB;
    const int gN = (NN + TPB - 1) / TPB;

    bool fork = g_ctx.ok;
    cudaStream_t sg = fork ? g_ctx.s2 : (cudaStream_t)0;

    if (fork) {
        cudaEventRecord(g_ctx.eF, 0);
        cudaStreamWaitEvent(sg, g_ctx.eF, 0);
    }

    // ===================== graph branch (stream sg) =====================
    cudaMemsetAsync(p_deg, 0, NN * sizeof(int), sg);
    deg_kernel<<<gE, TPB, 0, sg>>>(ei, p_deg);
    dis_kernel<<<gN, TPB, 0, sg>>>(p_deg, p_dis);

    // layer 1 (4 -> 4), hs1 in p_h
    transform1<<<gN, TPB, 0, sg>>>(x, W1, p_dis, p_h);
    cudaMemsetAsync(p_agg, 0, (size_t)NN * 4 * sizeof(float), sg);
    scatter_kernel<4><<<gE, TPB, 0, sg>>>(ei, p_h, p_agg);
    combine_transform<4, 8><<<gN, TPB, 0, sg>>>(p_agg, p_h, p_dis, b1, W2, p_feat);

    // layer 2 (4 -> 8), hs2 in p_feat
    cudaMemsetAsync(p_agg, 0, (size_t)NN * 8 * sizeof(float), sg);
    scatter_kernel<8><<<gE, TPB, 0, sg>>>(ei, p_feat, p_agg);
    combine_transform<8, 16><<<gN, TPB, 0, sg>>>(p_agg, p_feat, p_dis, b2, W3, p_h);

    // layer 3 (8 -> 16), hs3 in p_h
    cudaMemsetAsync(p_agg, 0, (size_t)NN * 16 * sizeof(float), sg);
    scatter_kernel<16><<<gE, TPB, 0, sg>>>(ei, p_h, p_agg);
    cudaMemsetAsync(p_pool, 0, BB * 16 * sizeof(float), sg);
    combine_pool<<<gN, TPB, 0, sg>>>(p_agg, p_h, p_dis, b3, batch, p_pool);

    // graph MLP -> xc[:, 0:128]
    gemm_kernel<<<dim3(16, 8), 256, 0, sg>>>(p_pool, Wg1, bg1, p_t1, BB, 16, 1024, 1024, 0, 1);
    gemm_kernel<<<dim3(2, 8), 256, 0, sg>>>(p_t1, Wg2, bg2, p_xc, BB, 1024, 128, 256, 0, 0);

    if (fork) cudaEventRecord(g_ctx.eJ, sg);

    // ===================== conv branch (stream 0) =====================
    conv1_kernel<<<dim3(BB, 14), dim3(32, 8)>>>(tgt, K1, cb1, p_c1);
    conv2_kernel<<<dim3(BB, 5, 2), dim3(32, 8)>>>(p_c1, K2, cb2, p_c2);
    cudaMemsetAsync(p_c3, 0, BB * 128 * sizeof(float));
    cudaFuncSetAttribute(conv3_kernel, cudaFuncAttributeMaxDynamicSharedMemorySize, CONV3_SMEM);
    conv3_kernel<<<dim3(BB, 4), dim3(32, 11), CONV3_SMEM>>>(p_c2, K3, cb3, p_c3);
    gemm_kernel<<<dim3(2, 8), 256>>>(p_c3, Wxt, bxt, p_xc, BB, 128, 128, 256, 128, 1);

    // ===================== join + fusion head (stream 0) =====================
    if (fork) cudaStreamWaitEvent(0, g_ctx.eJ, 0);
    gemm_kernel<<<dim3(16, 8), 256>>>(p_xc, Wf1, bf1, p_f1, BB, 256, 1024, 1024, 0, 1);
    gemm_kernel<<<dim3(8, 8), 256>>>(p_f1, Wf2, bf2, p_f2, BB, 1024, 512, 512, 0, 1);
    gemm_kernel<<<dim3(1, 8), 256>>>(p_f2, Wo, bo, out, BB, 512, 2, 2, 0, 0);
}

// round 3
// speedup vs baseline: 1.1798x; 1.0174x over previous
#include <cuda_runtime.h>
#include <cuda_bf16.h>
#include <cstdint>

#define NN 200000
#define EE 3200000
#define BB 512
#define LL 1000

typedef unsigned long long ull;

// ------------------------ scratch (device globals, no allocs) ---------------
__device__ float g_dis[NN];
__device__ int   g_deg[NN];
__device__ float g_h[NN * 16];
__device__ float g_feat[NN * 16];
__device__ float g_agg[NN * 16];
__device__ float g_pool[BB * 16];
__device__ float g_t1[BB * 1024];
__device__ float g_xc[BB * 256];
__device__ float g_c1[BB * 32 * 331];
__device__ float g_c2[BB * 64 * 108];
__device__ float g_c3[BB * 128];
__device__ float g_f1[BB * 1024];
__device__ float g_f2[BB * 512];

// ------------------------ f32x2 helpers --------------------------------------
__device__ __forceinline__ ull pk2(float lo, float hi) {
    ull r; asm("mov.b64 %0, {%1, %2};" : "=l"(r) : "f"(lo), "f"(hi)); return r;
}
__device__ __forceinline__ float2 upk2(ull v) {
    float2 r; asm("mov.b64 {%0, %1}, %2;" : "=f"(r.x), "=f"(r.y) : "l"(v)); return r;
}
__device__ __forceinline__ void ffma2(ull& d, ull a, ull b) {
    asm("fma.rn.f32x2 %0, %1, %2, %0;" : "+l"(d) : "l"(a), "l"(b));
}

// ------------------------ graph branch --------------------------------------
__global__ void deg_kernel(const int* __restrict__ ei, int* __restrict__ deg) {
    int e = blockIdx.x * blockDim.x + threadIdx.x;
    if (e >= EE) return;
    atomicAdd(&deg[ei[EE + e]], 1);
}

__global__ void dis_kernel(const int* __restrict__ deg, float* __restrict__ dis) {
    int i = blockIdx.x * blockDim.x + threadIdx.x;
    if (i >= NN) return;
    dis[i] = rsqrtf((float)deg[i] + 1.0f);
}

// hs = dis[i] * (x @ W1)
__global__ void transform1(const float* __restrict__ x, const float* __restrict__ W,
                           const float* __restrict__ dis, float* __restrict__ hs) {
    __shared__ float Ws[16];
    int tid = threadIdx.x;
    if (tid < 16) Ws[tid] = W[tid];
    __syncthreads();
    int i = blockIdx.x * blockDim.x + tid;
    if (i >= NN) return;
    float xi[4];
#pragma unroll
    for (int f = 0; f < 4; f++) xi[f] = x[(size_t)i * 4 + f];
    float dd = dis[i];
#pragma unroll
    for (int fo = 0; fo < 4; fo++) {
        float s = 0.f;
#pragma unroll
        for (int fi = 0; fi < 4; fi++) s = fmaf(xi[fi], Ws[fi * 4 + fo], s);
        hs[(size_t)i * 4 + fo] = dd * s;
    }
}

// pure copy-scatter: agg[dst] += hs[src]
template <int F>
__global__ void scatter_kernel(const int* __restrict__ ei, const float* __restrict__ hs,
                               float* __restrict__ agg) {
    int e = blockIdx.x * blockDim.x + threadIdx.x;
    if (e >= EE) return;
    int s = __ldg(&ei[e]);
    int d = __ldg(&ei[EE + e]);
    const float4* p = reinterpret_cast<const float4*>(hs + (size_t)s * F);
    float* ad = agg + (size_t)d * F;
#pragma unroll
    for (int q = 0; q < F / 4; q++) {
        float4 m = p[q];
        asm volatile("red.global.add.v4.f32 [%0], {%1,%2,%3,%4};"
                     :: "l"(ad + q * 4), "f"(m.x), "f"(m.y), "f"(m.z), "f"(m.w)
                     : "memory");
    }
}

// feat = relu(dis*(agg+hs)+b); out = dis * (feat @ W)
template <int F, int FO>
__global__ void combine_transform(const float* __restrict__ agg, const float* __restrict__ hs,
                                  const float* __restrict__ dis, const float* __restrict__ bias,
                                  const float* __restrict__ W, float* __restrict__ out) {
    __shared__ float Ws[F * FO];
    __shared__ float bs[F];
    int tid = threadIdx.x;
    if (tid < F * FO) Ws[tid] = W[tid];
    if (tid < F) bs[tid] = bias[tid];
    __syncthreads();
    int i = blockIdx.x * blockDim.x + tid;
    if (i >= NN) return;
    float dd = dis[i];
    float v[F];
#pragma unroll
    for (int f = 0; f < F; f++)
        v[f] = fmaxf(dd * (agg[(size_t)i * F + f] + hs[(size_t)i * F + f]) + bs[f], 0.f);
#pragma unroll
    for (int fo = 0; fo < FO; fo++) {
        float s = 0.f;
#pragma unroll
        for (int f = 0; f < F; f++) s = fmaf(v[f], Ws[f * FO + fo], s);
        out[(size_t)i * FO + fo] = dd * s;
    }
}

// final GCN layer + batch max pool
__global__ void combine_pool(const float* __restrict__ agg, const float* __restrict__ hs,
                             const float* __restrict__ dis, const float* __restrict__ bias,
                             const int* __restrict__ batch, float* __restrict__ pool) {
    __shared__ float bs[16];
    int tid = threadIdx.x;
    if (tid < 16) bs[tid] = bias[tid];
    __syncthreads();
    int i = blockIdx.x * blockDim.x + tid;
    if (i >= NN) return;
    float dd = dis[i];
    float v[16];
#pragma unroll
    for (int f = 0; f < 16; f++)
        v[f] = fmaxf(dd * (agg[(size_t)i * 16 + f] + hs[(size_t)i * 16 + f]) + bs[f], 0.f);
    int bb = batch[i];
    unsigned m = __activemask();
    bool uni = false;
    if (m == 0xffffffffu) {
        int bb0 = __shfl_sync(0xffffffffu, bb, 0);
        uni = __all_sync(0xffffffffu, bb == bb0);
    }
    int* p = reinterpret_cast<int*>(pool + (size_t)bb * 16);
    if (uni) {
#pragma unroll
        for (int f = 0; f < 16; f++) {
            float t = v[f];
#pragma unroll
            for (int o = 16; o; o >>= 1) t = fmaxf(t, __shfl_xor_sync(0xffffffffu, t, o));
            v[f] = t;
        }
        if ((tid & 31) == 0)
#pragma unroll
            for (int f = 0; f < 16; f++) atomicMax(&p[f], __float_as_int(v[f]));
    } else {
#pragma unroll
        for (int f = 0; f < 16; f++) atomicMax(&p[f], __float_as_int(v[f]));
    }
}

// ------------------------ generic GEMM (f32x2, vectorized LDS) --------------
__global__ void gemm_kernel(const float* __restrict__ A, const float* __restrict__ W,
                            const float* __restrict__ bias, float* __restrict__ C,
                            int M, int K, int Nc, int ldc, int coloff, int relu) {
    const int BM = 64, BN = 64, BK = 8;
    __shared__ __align__(16) float As[BK][BM];
    __shared__ __align__(16) float Bs[BK][BN];
    int tid = threadIdx.x;
    int tc = tid & 15, tr = tid >> 4;
    int brow = blockIdx.y * BM, bcol = blockIdx.x * BN;
    ull acc[4][2] = {};
    for (int k0 = 0; k0 < K; k0 += BK) {
        for (int i = tid; i < BM * BK; i += 256) {
            int kk = i & 7, m = i >> 3;
            int gr = brow + m, gc = k0 + kk;
            As[kk][m] = (gr < M && gc < K) ? A[(size_t)gr * K + gc] : 0.f;
        }
        for (int i = tid; i < BN * BK; i += 256) {
            int n = i & 63, kk = i >> 6;
            int gc = bcol + n, gr = k0 + kk;
            Bs[kk][n] = (gr < K && gc < Nc) ? W[(size_t)gr * Nc + gc] : 0.f;
        }
        __syncthreads();
#pragma unroll
        for (int kk = 0; kk < BK; kk++) {
            ull b0 = *reinterpret_cast<const ull*>(&Bs[kk][tc * 4]);
            ull b1 = *reinterpret_cast<const ull*>(&Bs[kk][tc * 4 + 2]);
            float4 av = *reinterpret_cast<const float4*>(&As[kk][tr * 4]);
            float aa[4] = {av.x, av.y, av.z, av.w};
#pragma unroll
            for (int u = 0; u < 4; u++) {
                ull a2 = pk2(aa[u], aa[u]);
                ffma2(acc[u][0], b0, a2);
                ffma2(acc[u][1], b1, a2);
            }
        }
        __syncthreads();
    }
#pragma unroll
    for (int u = 0; u < 4; u++) {
        int r = brow + tr * 4 + u;
        if (r >= M) continue;
#pragma unroll
        for (int v2 = 0; v2 < 2; v2++) {
            float2 pv = upk2(acc[u][v2]);
            float vals[2] = {pv.x, pv.y};
#pragma unroll
            for (int w = 0; w < 2; w++) {
                int c = bcol + tc * 4 + v2 * 2 + w;
                if (c >= Nc) continue;
                float val = vals[w] + bias[c];
                if (relu) val = fmaxf(val, 0.f);
                C[(size_t)r * ldc + coloff + c] = val;
            }
        }
    }
}

// ------------------------ conv inner (f32x2, LDS.128 inputs) -----------------
// xp: 16 contiguous, 16B-aligned floats; w: &w_s[ic*K8*32 + tx] stride 32.
__device__ __forceinline__ void ic_update(const float* __restrict__ xp,
                                          const float* __restrict__ w, ull acc[5]) {
    float4 x0 = *reinterpret_cast<const float4*>(xp);
    float4 x1 = *reinterpret_cast<const float4*>(xp + 4);
    float4 x2 = *reinterpret_cast<const float4*>(xp + 8);
    float4 x3 = *reinterpret_cast<const float4*>(xp + 12);
    float xr[16] = {x0.x, x0.y, x0.z, x0.w, x1.x, x1.y, x1.z, x1.w,
                    x2.x, x2.y, x2.z, x2.w, x3.x, x3.y, x3.z, x3.w};
    ull e[8], o[8];
#pragma unroll
    for (int i = 0; i < 8; i++) e[i] = pk2(xr[2 * i], xr[2 * i + 1]);
#pragma unroll
    for (int i = 0; i < 7; i++) o[i] = pk2(xr[2 * i + 1], xr[2 * i + 2]);
    o[7] = pk2(xr[15], 0.f);
#pragma unroll
    for (int k = 0; k < 8; k++) {
        float wv = w[k * 32];
        ull w2 = pk2(wv, wv);
        const ull* xpp = (k & 1) ? &o[k >> 1] : &e[k >> 1];
#pragma unroll
        for (int j = 0; j < 5; j++) ffma2(acc[j], xpp[j], w2);
    }
}

__device__ __forceinline__ void unpack9(const ull acc[5], float a[9]) {
#pragma unroll
    for (int j = 0; j < 4; j++) {
        float2 t = upk2(acc[j]);
        a[2 * j] = t.x; a[2 * j + 1] = t.y;
    }
    a[8] = upk2(acc[4]).x;
}

// conv1: target [B,L,5] -> conv(k=8)+relu+maxpool3 -> [B,32,331]
__global__ void conv1_kernel(const float* __restrict__ tgt, const float* __restrict__ K1,
                             const float* __restrict__ cb1, float* __restrict__ out) {
    __shared__ __align__(16) float in_s[5 * 8 * 16];   // [ic][ty][16] duplicated
    __shared__ float w_s[5 * 8 * 32];
    __shared__ float b_s[32];
    int b = blockIdx.x;
    int g0 = blockIdx.y * 8;
    int tx = threadIdx.x, ty = threadIdx.y;
    int tid = ty * 32 + tx;
    int L0 = g0 * 9;
    for (int i = tid; i < 5 * 8 * 16; i += 256) {
        int c = i >> 7, t = (i >> 4) & 7, j = i & 15;
        int l = L0 + t * 9 + j;
        in_s[i] = (l < LL) ? tgt[(size_t)b * (LL * 5) + l * 5 + c] : 0.f;
    }
    for (int i = tid; i < 1280; i += 256) {
        int oc = i / 40, r = i % 40;
        w_s[r * 32 + oc] = K1[i];
    }
    if (tid < 32) b_s[tid] = cb1[tid];
    __syncthreads();

    ull acc[5] = {};
#pragma unroll
    for (int ic = 0; ic < 5; ic++)
        ic_update(&in_s[(ic * 8 + ty) * 16], &w_s[ic * 256 + tx], acc);
    float a[9]; unpack9(acc, a);
    float bb = b_s[tx];
    int grp = g0 + ty;
#pragma unroll
    for (int p = 0; p < 3; p++) {
        int po = grp * 3 + p;
        if (po < 331) {
            float v = fmaxf(fmaxf(a[3 * p], a[3 * p + 1]), a[3 * p + 2]) + bb;
            out[((size_t)b * 32 + tx) * 331 + po] = fmaxf(v, 0.f);
        }
    }
}

// conv2: [B,32,331] -> conv(k=8)+relu+pool3 -> [B,64,108]
__global__ void conv2_kernel(const float* __restrict__ c1, const float* __restrict__ K2,
                             const float* __restrict__ cb2, float* __restrict__ out) {
    __shared__ __align__(16) float in_s[32 * 8 * 16];  // 16 KB, [ic][ty][16]
    __shared__ float w_s[32 * 8 * 32];                 // 32 KB
    __shared__ float b_s[32];
    int b = blockIdx.x;
    int g0 = blockIdx.y * 8;
    int ocz = blockIdx.z;
    int tx = threadIdx.x, ty = threadIdx.y;
    int tid = ty * 32 + tx;
    int L0 = g0 * 9;
    for (int i = tid; i < 32 * 8 * 16; i += 256) {
        int ic = i >> 7, t = (i >> 4) & 7, j = i & 15;
        int l = L0 + t * 9 + j;
        in_s[i] = (l < 331) ? c1[((size_t)b * 32 + ic) * 331 + l] : 0.f;
    }
    for (int i = tid; i < 8192; i += 256) {
        int oc = i / 256, r = i % 256;
        w_s[r * 32 + oc] = K2[((size_t)(ocz * 32 + oc)) * 256 + r];
    }
    if (tid < 32) b_s[tid] = cb2[ocz * 32 + tid];
    __syncthreads();

    int grp = g0 + ty;
    ull acc[5] = {};
#pragma unroll 2
    for (int ic = 0; ic < 32; ic++)
        ic_update(&in_s[(ic * 8 + ty) * 16], &w_s[ic * 256 + tx], acc);
    if (grp < 36) {
        float a[9]; unpack9(acc, a);
        float bb = b_s[tx];
        int oc = ocz * 32 + tx;
#pragma unroll
        for (int p = 0; p < 3; p++) {
            int po = grp * 3 + p;
            float v = fmaxf(fmaxf(a[3 * p], a[3 * p + 1]), a[3 * p + 2]) + bb;
            out[((size_t)b * 64 + oc) * 108 + po] = fmaxf(v, 0.f);
        }
    }
}

// conv3: [B,64,108] -> conv(k=8)+relu+pool3 -> mean over 33 -> [B,128]
#define CONV3_SMEM ((64 * 11 * 16 + 16384 + 32) * 4)
__global__ void conv3_kernel(const float* __restrict__ c2, const float* __restrict__ K3,
                             const float* __restrict__ cb3, float* __restrict__ c3) {
    extern __shared__ __align__(16) float sm[];
    float* in_s = sm;               // [ic][ty(11)][16]
    float* w_s = sm + 64 * 11 * 16; // [(ic*8+k)*32+oc]
    float* b_s = w_s + 16384;
    int b = blockIdx.x;
    int ocz = blockIdx.y;
    int tx = threadIdx.x, ty = threadIdx.y;
    int tid = ty * 32 + tx;         // 352 threads
    for (int i = tid; i < 64 * 11 * 16; i += 352) {
        int ic = i / 176, r = i % 176, t = r / 16, j = r % 16;
        in_s[i] = c2[(size_t)b * 6912 + ic * 108 + t * 9 + j];
    }
    for (int i = tid; i < 16384; i += 352) {
        int oc = i / 512, r = i % 512;
        w_s[r * 32 + oc] = K3[((size_t)(ocz * 32 + oc)) * 512 + r];
    }
    if (tid < 32) b_s[tid] = cb3[ocz * 32 + tid];
    __syncthreads();

    ull acc[5] = {};
#pragma unroll 2
    for (int ic = 0; ic < 64; ic++)
        ic_update(&in_s[(ic * 11 + ty) * 16], &w_s[ic * 256 + tx], acc);
    float a[9]; unpack9(acc, a);
    float bb = b_s[tx];
    float s = 0.f;
#pragma unroll
    for (int p = 0; p < 3; p++) {
        float v = fmaxf(fmaxf(a[3 * p], a[3 * p + 1]), a[3 * p + 2]) + bb;
        s += fmaxf(v, 0.f);
    }
    atomicAdd(&c3[(size_t)b * 128 + ocz * 32 + tx], s * (1.0f / 33.0f));
}

// ------------------------ stream fork/join context --------------------------
struct Ctx {
    cudaStream_t s2 = nullptr;
    cudaEvent_t eF = nullptr, eJ = nullptr;
    bool ok = false;
    Ctx() {
        ok = (cudaStreamCreateWithFlags(&s2, cudaStreamNonBlocking) == cudaSuccess) &&
             (cudaEventCreateWithFlags(&eF, cudaEventDisableTiming) == cudaSuccess) &&
             (cudaEventCreateWithFlags(&eJ, cudaEventDisableTiming) == cudaSuccess);
    }
};
static Ctx g_ctx;

// ------------------------ host orchestration --------------------------------
extern "C" void kernel_launch(void* const* d_in, const int* in_sizes, int n_in,
                              void* d_out, int out_size) {
    const float* x    = (const float*)d_in[0];
    const int*   ei   = (const int*)d_in[1];
    const int*   batch= (const int*)d_in[2];
    const float* tgt  = (const float*)d_in[3];
    const float* W1 = (const float*)d_in[4];   const float* b1 = (const float*)d_in[5];
    const float* W2 = (const float*)d_in[6];   const float* b2 = (const float*)d_in[7];
    const float* W3 = (const float*)d_in[8];   const float* b3 = (const float*)d_in[9];
    const float* Wg1= (const float*)d_in[10];  const float* bg1= (const float*)d_in[11];
    const float* Wg2= (const float*)d_in[12];  const float* bg2= (const float*)d_in[13];
    const float* K1 = (const float*)d_in[14];  const float* cb1= (const float*)d_in[15];
    const float* K2 = (const float*)d_in[16];  const float* cb2= (const float*)d_in[17];
    const float* K3 = (const float*)d_in[18];  const float* cb3= (const float*)d_in[19];
    const float* Wxt= (const float*)d_in[20];  const float* bxt= (const float*)d_in[21];
    const float* Wf1= (const float*)d_in[22];  const float* bf1= (const float*)d_in[23];
    const float* Wf2= (const float*)d_in[24];  const float* bf2= (const float*)d_in[25];
    const float* Wo = (const float*)d_in[26];  const float* bo = (const float*)d_in[27];
    float* out = (float*)d_out;

    float *p_dis, *p_h, *p_feat, *p_agg, *p_pool, *p_t1, *p_xc, *p_c1, *p_c2, *p_c3, *p_f1, *p_f2;
    int* p_deg;
    cudaGetSymbolAddress((void**)&p_dis, g_dis);
    cudaGetSymbolAddress((void**)&p_deg, g_deg);
    cudaGetSymbolAddress((void**)&p_h, g_h);
    cudaGetSymbolAddress((void**)&p_feat, g_feat);
    cudaGetSymbolAddress((void**)&p_agg, g_agg);
    cudaGetSymbolAddress((void**)&p_pool, g_pool);
    cudaGetSymbolAddress((void**)&p_t1, g_t1);
    cudaGetSymbolAddress((void**)&p_xc, g_xc);
    cudaGetSymbolAddress((void**)&p_c1, g_c1);
    cudaGetSymbolAddress((void**)&p_c2, g_c2);
    cudaGetSymbolAddress((void**)&p_c3, g_c3);
    cudaGetSymbolAddress((void**)&p_f1, g_f1);
    cudaGetSymbolAddress((void**)&p_f2, g_f2);

    const int TPB = 256;
    const int gE = (EE + TPB - 1) / TPB;
    const int gN = (NN + TPB - 1) / TPB;

    bool fork = g_ctx.ok;
    cudaStream_t sg = fork ? g_ctx.s2 : (cudaStream_t)0;

    if (fork) {
        cudaEventRecord(g_ctx.eF, 0);
        cudaStreamWaitEvent(sg, g_ctx.eF, 0);
    }

    // Launch order matters for ncu (-s 5 -c 1 profiles the 6th launch = conv2).
    // #1..#4 on graph stream:
    cudaMemsetAsync(p_deg, 0, NN * sizeof(int), sg);               // 1
    deg_kernel<<<gE, TPB, 0, sg>>>(ei, p_deg);                     // 2
    dis_kernel<<<gN, TPB, 0, sg>>>(p_deg, p_dis);                  // 3
    transform1<<<gN, TPB, 0, sg>>>(x, W1, p_dis, p_h);             // 4
    // #5, #6 on conv stream:
    conv1_kernel<<<dim3(BB, 14), dim3(32, 8)>>>(tgt, K1, cb1, p_c1);            // 5
    conv2_kernel<<<dim3(BB, 5, 2), dim3(32, 8)>>>(p_c1, K2, cb2, p_c2);         // 6 <- profiled

    // ---- rest of graph branch (stream sg) ----
    cudaMemsetAsync(p_agg, 0, (size_t)NN * 4 * sizeof(float), sg);
    scatter_kernel<4><<<gE, TPB, 0, sg>>>(ei, p_h, p_agg);
    combine_transform<4, 8><<<gN, TPB, 0, sg>>>(p_agg, p_h, p_dis, b1, W2, p_feat);

    cudaMemsetAsync(p_agg, 0, (size_t)NN * 8 * sizeof(float), sg);
    scatter_kernel<8><<<gE, TPB, 0, sg>>>(ei, p_feat, p_agg);
    combine_transform<8, 16><<<gN, TPB, 0, sg>>>(p_agg, p_feat, p_dis, b2, W3, p_h);

    cudaMemsetAsync(p_agg, 0, (size_t)NN * 16 * sizeof(float), sg);
    scatter_kernel<16><<<gE, TPB, 0, sg>>>(ei, p_h, p_agg);
    cudaMemsetAsync(p_pool, 0, BB * 16 * sizeof(float), sg);
    combine_pool<<<gN, TPB, 0, sg>>>(p_agg, p_h, p_dis, b3, batch, p_pool);

    gemm_kernel<<<dim3(16, 8), 256, 0, sg>>>(p_pool, Wg1, bg1, p_t1, BB, 16, 1024, 1024, 0, 1);
    gemm_kernel<<<dim3(2, 8), 256, 0, sg>>>(p_t1, Wg2, bg2, p_xc, BB, 1024, 128, 256, 0, 0);
    if (fork) cudaEventRecord(g_ctx.eJ, sg);

    // ---- rest of conv branch (stream 0) ----
    cudaMemsetAsync(p_c3, 0, BB * 128 * sizeof(float));
    cudaFuncSetAttribute(conv3_kernel, cudaFuncAttributeMaxDynamicSharedMemorySize, CONV3_SMEM);
    conv3_kernel<<<dim3(BB, 4), dim3(32, 11), CONV3_SMEM>>>(p_c2, K3, cb3, p_c3);
    gemm_kernel<<<dim3(2, 8), 256>>>(p_c3, Wxt, bxt, p_xc, BB, 128, 128, 256, 128, 1);

    // ---- join + fusion head (stream 0) ----
    if (fork) cudaStreamWaitEvent(0, g_ctx.eJ, 0);
    gemm_kernel<<<dim3(16, 8), 256>>>(p_xc, Wf1, bf1, p_f1, BB, 256, 1024, 1024, 0, 1);
    gemm_kernel<<<dim3(8, 8), 256>>>(p_f1, Wf2, bf2, p_f2, BB, 1024, 512, 512, 0, 1);
    gemm_kernel<<<dim3(1, 8), 256>>>(p_f2, Wo, bo, out, BB, 512, 2, 2, 0, 0);
}